// round 4
// baseline (speedup 1.0000x reference)
#include <cuda_runtime.h>

#define NN 100000
#define NE 1600000
#define CAP 128
#define NF1 128
#define NH  64
#define NC  40

typedef unsigned long long ull;

// -------- scratch (device globals; no allocation allowed) --------
__device__ float g_deg[NN];
__device__ int   g_cnt[NN];
__device__ int2  g_slot[(long long)NN * CAP];   // (src_row, float_bits(dinv[src]*w))
__device__ float g_h1[(long long)NN * NH];      // x @ W1
__device__ float g_out1[(long long)NN * NH];    // relu(aggregate + b1)
__device__ float g_h2[(long long)NN * NC];      // out1 @ W2

// -------- packed f32x2 helpers --------
__device__ __forceinline__ ull pack2(float x, float y) {
    ull r;
    asm("mov.b64 %0, {%1, %2};" : "=l"(r) : "f"(x), "f"(y));
    return r;
}
__device__ __forceinline__ void fma2(ull& d, ull a, ull b) {
    asm("fma.rn.f32x2 %0, %1, %2, %0;" : "+l"(d) : "l"(a), "l"(b));
}
__device__ __forceinline__ float2 unpack2(ull v) {
    float2 f;
    asm("mov.b64 {%0, %1}, %2;" : "=f"(f.x), "=f"(f.y) : "l"(v));
    return f;
}

// -------- prep kernels --------
__global__ void k_init() {
    int n = blockIdx.x * blockDim.x + threadIdx.x;
    if (n < NN) { g_deg[n] = 1.0f; g_cnt[n] = 0; }  // self-loop weight 1
}

__global__ void k_deg(const int* __restrict__ ei, const float* __restrict__ ew) {
    int e = blockIdx.x * blockDim.x + threadIdx.x;
    if (e < NE) {
        int c = ei[NE + e];
        if (c >= 0 && c < NN) atomicAdd(&g_deg[c], ew[e]);
    }
}

__global__ void k_place(const int* __restrict__ ei, const float* __restrict__ ew) {
    int e = blockIdx.x * blockDim.x + threadIdx.x;
    if (e >= NE) return;
    int r = ei[e];
    int c = ei[NE + e];
    if (r < 0 || r >= NN || c < 0 || c >= NN) return;
    float dr = rsqrtf(g_deg[r]);          // deg >= 1 always (self loop)
    float pnorm = dr * ew[e];             // dinv[c] factored out; applied in gather
    int pos = atomicAdd(&g_cnt[c], 1);
    if (pos < CAP) {
        int2 s;
        s.x = r;
        s.y = __float_as_int(pnorm);
        g_slot[(long long)c * CAP + pos] = s;
    }
}

// -------- GEMM1: g_h1[N,64] = x[N,128] @ W1[128,64] --------
// 256 threads, 64-row block, 4x4 register tile (f32x2 packed).
// A staged TRANSPOSED in smem: sAT[k][r], stride 66 -> 2x LDS.64 per k.
__global__ void gemm1(const float* __restrict__ A, const float* __restrict__ B) {
    __shared__ __align__(16) float sAT[64][66];   // [k][row]
    __shared__ __align__(16) float sB[64][64];    // [k][col]
    int tid = threadIdx.x;
    int tx = tid & 15, ty = tid >> 4;
    int row0 = blockIdx.x * 64;
    ull acc2[4][2] = {};   // bits(0,0) == 0.0f pair

    for (int kc = 0; kc < 2; kc++) {
#pragma unroll
        for (int t = 0; t < 4; t++) {
            int lin = (t * 256 + tid) * 4;   // 0..4095
            int r  = lin >> 6;               // 0..63
            int k0 = lin & 63;
            int grow = row0 + r;
            float4 v = make_float4(0.f, 0.f, 0.f, 0.f);
            if (grow < NN) v = *(const float4*)&A[(long long)grow * NF1 + kc * 64 + k0];
            sAT[k0 + 0][r] = v.x;
            sAT[k0 + 1][r] = v.y;
            sAT[k0 + 2][r] = v.z;
            sAT[k0 + 3][r] = v.w;
            float4 w = *(const float4*)&B[(kc * 64 + r) * NH + k0];
            *(float4*)&sB[r][k0] = w;
        }
        __syncthreads();
#pragma unroll
        for (int k = 0; k < 64; k++) {
            float2 a01 = *(const float2*)&sAT[k][ty * 4];
            float2 a23 = *(const float2*)&sAT[k][ty * 4 + 2];
            ulonglong2 bb = *(const ulonglong2*)&sB[k][tx * 4];
            fma2(acc2[0][0], pack2(a01.x, a01.x), bb.x);
            fma2(acc2[0][1], pack2(a01.x, a01.x), bb.y);
            fma2(acc2[1][0], pack2(a01.y, a01.y), bb.x);
            fma2(acc2[1][1], pack2(a01.y, a01.y), bb.y);
            fma2(acc2[2][0], pack2(a23.x, a23.x), bb.x);
            fma2(acc2[2][1], pack2(a23.x, a23.x), bb.y);
            fma2(acc2[3][0], pack2(a23.y, a23.y), bb.x);
            fma2(acc2[3][1], pack2(a23.y, a23.y), bb.y);
        }
        __syncthreads();
    }
#pragma unroll
    for (int i = 0; i < 4; i++) {
        int grow = row0 + ty * 4 + i;
        if (grow < NN) {
            float2 lo = unpack2(acc2[i][0]);
            float2 hi = unpack2(acc2[i][1]);
            float4 v = make_float4(lo.x, lo.y, hi.x, hi.y);
            *(float4*)&g_h1[(long long)grow * NH + tx * 4] = v;
        }
    }
}

// -------- GEMM2: g_h2[N,40] = g_out1[N,64] @ W2[64,40] --------
// 160 threads (16 x 10), 64-row block, 4x4 register tile (f32x2), K=64, transposed A.
__global__ void gemm2(const float* __restrict__ B) {
    __shared__ __align__(16) float sAT[64][66];   // [k][row]
    __shared__ __align__(16) float sB[64 * 40];   // [k][col]
    int tid = threadIdx.x;           // 0..159
    int tx = tid % 10, ty = tid / 10;
    int row0 = blockIdx.x * 64;

    for (int idx = tid; idx < 1024; idx += 160) {   // 64 rows x 16 float4
        int r  = idx >> 4;
        int k0 = (idx & 15) << 2;
        int grow = row0 + r;
        float4 v = make_float4(0.f, 0.f, 0.f, 0.f);
        if (grow < NN) v = *(const float4*)&g_out1[(long long)grow * NH + k0];
        sAT[k0 + 0][r] = v.x;
        sAT[k0 + 1][r] = v.y;
        sAT[k0 + 2][r] = v.z;
        sAT[k0 + 3][r] = v.w;
    }
    for (int idx = tid; idx < 64 * 40; idx += 160) sB[idx] = B[idx];
    __syncthreads();

    ull acc2[4][2] = {};
#pragma unroll
    for (int k = 0; k < 64; k++) {
        float2 a01 = *(const float2*)&sAT[k][ty * 4];
        float2 a23 = *(const float2*)&sAT[k][ty * 4 + 2];
        ulonglong2 bb = *(const ulonglong2*)&sB[k * 40 + tx * 4];
        fma2(acc2[0][0], pack2(a01.x, a01.x), bb.x);
        fma2(acc2[0][1], pack2(a01.x, a01.x), bb.y);
        fma2(acc2[1][0], pack2(a01.y, a01.y), bb.x);
        fma2(acc2[1][1], pack2(a01.y, a01.y), bb.y);
        fma2(acc2[2][0], pack2(a23.x, a23.x), bb.x);
        fma2(acc2[2][1], pack2(a23.x, a23.x), bb.y);
        fma2(acc2[3][0], pack2(a23.y, a23.y), bb.x);
        fma2(acc2[3][1], pack2(a23.y, a23.y), bb.y);
    }
#pragma unroll
    for (int i = 0; i < 4; i++) {
        int grow = row0 + ty * 4 + i;
        if (grow < NN) {
            float2 lo = unpack2(acc2[i][0]);
            float2 hi = unpack2(acc2[i][1]);
            float4 v = make_float4(lo.x, lo.y, hi.x, hi.y);
            *(float4*)&g_h2[(long long)grow * NC + tx * 4] = v;
        }
    }
}

// -------- gather layer 1: warp per node, float2 lanes, paired slot loads --------
// out1[n][j] = relu(dc*(sum pnorm*h1[r][j] + dc*h1[n][j]) + b1[j]),  dc = dinv[n]
__global__ void gather1(const float* __restrict__ b1) {
    int node = blockIdx.x * 8 + (threadIdx.x >> 5);
    if (node >= NN) return;
    int lane = threadIdx.x & 31;
    float dc = rsqrtf(g_deg[node]);
    int c = min(g_cnt[node], CAP);
    const int2* slots = &g_slot[(long long)node * CAP];
    ull acc = 0;
    int k = 0;
    for (; k + 2 <= c; k += 2) {
        int4 s2 = *(const int4*)&slots[k];   // 16B aligned (k even, base 1024B aligned)
        float n0 = __int_as_float(s2.y);
        float n1 = __int_as_float(s2.w);
        ull h0 = *(const ull*)&g_h1[(long long)s2.x * NH + lane * 2];
        ull h1v = *(const ull*)&g_h1[(long long)s2.z * NH + lane * 2];
        fma2(acc, pack2(n0, n0), h0);
        fma2(acc, pack2(n1, n1), h1v);
    }
    if (k < c) {
        int2 s = slots[k];
        float nm = __int_as_float(s.y);
        ull h = *(const ull*)&g_h1[(long long)s.x * NH + lane * 2];
        fma2(acc, pack2(nm, nm), h);
    }
    float2 a = unpack2(acc);
    float2 self = *(const float2*)&g_h1[(long long)node * NH + lane * 2];
    float ox = fmaf(dc, fmaf(dc, self.x, a.x), __ldg(&b1[lane * 2]));
    float oy = fmaf(dc, fmaf(dc, self.y, a.y), __ldg(&b1[lane * 2 + 1]));
    float2 o = make_float2(fmaxf(ox, 0.f), fmaxf(oy, 0.f));
    *(float2*)&g_out1[(long long)node * NH + lane * 2] = o;
}

// -------- gather layer 2: warp per node, lanes 0..19 (float2), paired slots --------
__global__ void gather2(const float* __restrict__ b2, float* __restrict__ out) {
    int node = blockIdx.x * 8 + (threadIdx.x >> 5);
    if (node >= NN) return;
    int lane = threadIdx.x & 31;
    if (lane >= 20) return;
    float dc = rsqrtf(g_deg[node]);
    int c = min(g_cnt[node], CAP);
    const int2* slots = &g_slot[(long long)node * CAP];
    ull acc = 0;
    int k = 0;
    for (; k + 2 <= c; k += 2) {
        int4 s2 = *(const int4*)&slots[k];
        float n0 = __int_as_float(s2.y);
        float n1 = __int_as_float(s2.w);
        ull h0 = *(const ull*)&g_h2[(long long)s2.x * NC + lane * 2];
        ull h1v = *(const ull*)&g_h2[(long long)s2.z * NC + lane * 2];
        fma2(acc, pack2(n0, n0), h0);
        fma2(acc, pack2(n1, n1), h1v);
    }
    if (k < c) {
        int2 s = slots[k];
        float nm = __int_as_float(s.y);
        ull h = *(const ull*)&g_h2[(long long)s.x * NC + lane * 2];
        fma2(acc, pack2(nm, nm), h);
    }
    float2 a = unpack2(acc);
    float2 self = *(const float2*)&g_h2[(long long)node * NC + lane * 2];
    float2 o;
    o.x = fmaf(dc, fmaf(dc, self.x, a.x), __ldg(&b2[lane * 2]));
    o.y = fmaf(dc, fmaf(dc, self.y, a.y), __ldg(&b2[lane * 2 + 1]));
    *(float2*)&out[(long long)node * NC + lane * 2] = o;
}

extern "C" void kernel_launch(void* const* d_in, const int* in_sizes, int n_in,
                              void* d_out, int out_size) {
    const float* x  = (const float*)d_in[0];
    const int*   ei = (const int*)d_in[1];     // int32 (JAX default x64-disabled)
    const float* ew = (const float*)d_in[2];
    const float* W1 = (const float*)d_in[3];
    const float* b1 = (const float*)d_in[4];
    const float* W2 = (const float*)d_in[5];
    const float* b2 = (const float*)d_in[6];
    float* out = (float*)d_out;

    (void)in_sizes; (void)n_in; (void)out_size;

    k_init<<<(NN + 255) / 256, 256>>>();
    k_deg<<<(NE + 255) / 256, 256>>>(ei, ew);
    k_place<<<(NE + 255) / 256, 256>>>(ei, ew);

    gemm1<<<(NN + 63) / 64, 256>>>(x, W1);
    gather1<<<(NN + 7) / 8, 256>>>(b1);

    gemm2<<<(NN + 63) / 64, 160>>>(W2);
    gather2<<<(NN + 7) / 8, 256>>>(b2, out);
}